// round 6
// baseline (speedup 1.0000x reference)
#include <cuda_runtime.h>
#include <cuda_fp16.h>
#include <cstdint>

// ============================================================================
// MHMLP: out[b,h] = lrelu( sum_n lrelu( x[b,:]·W1[h,:,n] + b1[h,n] ) * W2[h,n] + b2[h] )
// B=2048, H=64, D=512(K), HID=2048(N). fp32 in/out, fp16 HMMA compute.
// R6: one CTA = FOUR independent pipeline quarters (2m x 2n), each 4 warps,
// own W double-buffer (32k x 128n chunks), own named barrier. Warp->SMSP map
// puts one warp of each quarter on every SMSP: a barrier convoy in one
// quarter leaves 3 independent warps per scheduler feeding the tensor pipe.
// ============================================================================
#define BB   2048
#define HH   64
#define DD   512
#define HID  2048

__device__ __half  g_W16[(size_t)HH * DD * HID];    // [h][d][n] fp16
__device__ __half  g_X16[(size_t)BB * DD];          // [b][d]   fp16
__device__ float4  g_BW4[(size_t)HH * HID / 2];     // {b1[n],w2[n],b1[n+1],w2[n+1]}

__device__ __forceinline__ uint32_t smem_to_u32(const void* p) {
    uint32_t a;
    asm("{ .reg .u64 t; cvta.to.shared.u64 t, %1; cvt.u32.u64 %0, t; }" : "=r"(a) : "l"(p));
    return a;
}
__device__ __forceinline__ void cp_async_16(uint32_t dst, const void* src) {
    asm volatile("cp.async.cg.shared.global [%0], [%1], 16;" :: "r"(dst), "l"(src));
}
#define CP_COMMIT()  asm volatile("cp.async.commit_group;" ::: "memory")
#define CP_WAIT_ALL() asm volatile("cp.async.wait_group 0;" ::: "memory")

#define LDSM_X4(r0, r1, r2, r3, addr) \
    asm volatile("ldmatrix.sync.aligned.m8n8.x4.shared.b16 {%0,%1,%2,%3}, [%4];" \
        : "=r"(r0), "=r"(r1), "=r"(r2), "=r"(r3) : "r"(addr))
#define LDSM_X4_T(r0, r1, r2, r3, addr) \
    asm volatile("ldmatrix.sync.aligned.m8n8.x4.trans.shared.b16 {%0,%1,%2,%3}, [%4];" \
        : "=r"(r0), "=r"(r1), "=r"(r2), "=r"(r3) : "r"(addr))

__device__ __forceinline__ void mma16816(float* c, const uint32_t* a, const uint32_t* b) {
    asm volatile(
        "mma.sync.aligned.m16n8k16.row.col.f32.f16.f16.f32 "
        "{%0,%1,%2,%3}, {%4,%5,%6,%7}, {%8,%9}, {%0,%1,%2,%3};"
        : "+f"(c[0]), "+f"(c[1]), "+f"(c[2]), "+f"(c[3])
        : "r"(a[0]), "r"(a[1]), "r"(a[2]), "r"(a[3]), "r"(b[0]), "r"(b[1]));
}

__device__ __forceinline__ float lrelu(float v) {
    return fmaxf(v, 0.f) + 0.01f * fminf(v, 0.f);
}

// ============================================================================
// Merged pre-pass:
//   blocks [0,512):       x fp32 -> fp16
//   blocks [512,33280):   W1 fp32 -> fp16
//   blocks [33280,33312): build g_BW4 (b1/W2 interleaved)
// ============================================================================
__global__ void convert_all_kernel(const float* __restrict__ x,
                                   const float* __restrict__ W1,
                                   const float* __restrict__ b1,
                                   const float* __restrict__ w2) {
    if (blockIdx.x >= 33280) {
        int g = (blockIdx.x - 33280) * 256 + threadIdx.x;   // 8192 threads
        float2* bw2 = reinterpret_cast<float2*>(g_BW4);
#pragma unroll
        for (int i = 0; i < 16; ++i) {
            int e = g + i * 8192;                           // HH*HID = 131072
            bw2[e] = make_float2(b1[e], w2[e]);
        }
        return;
    }
    const float* src;
    __half* dst;
    size_t g;
    if (blockIdx.x < 512) {
        g = (size_t)blockIdx.x * 256 + threadIdx.x;
        src = x;  dst = g_X16;
    } else {
        g = (size_t)(blockIdx.x - 512) * 256 + threadIdx.x;
        src = W1; dst = g_W16;
    }
    const float4* p = reinterpret_cast<const float4*>(src) + g * 2;
    float4 a = p[0], b = p[1];
    __half2 h0 = __floats2half2_rn(a.x, a.y), h1 = __floats2half2_rn(a.z, a.w);
    __half2 h2 = __floats2half2_rn(b.x, b.y), h3 = __floats2half2_rn(b.z, b.w);
    uint4 o;
    o.x = *reinterpret_cast<uint32_t*>(&h0);
    o.y = *reinterpret_cast<uint32_t*>(&h1);
    o.z = *reinterpret_cast<uint32_t*>(&h2);
    o.w = *reinterpret_cast<uint32_t*>(&h3);
    *reinterpret_cast<uint4*>(dst + g * 8) = o;
}

// ============================================================================
// Main fused kernel
// Grid: 1024 = 64 heads x 16 m-tiles. 512 threads = 16 warps = 4 quarters.
// Quarter q = (qm, qn): qm = 64-row half, qn = 1024-col half. Within quarter:
// 4 warps (2m x 2n), warp tile 32m x 64n. Per quarter: 128 t-iterations
// (8 n-chunks of 128n x 16 k-chunks of 32k), own W double buffer (8KB chunks),
// own named barrier (128 threads). X tile shared, read-only after init.
//
// SMEM:
//   [0..131072)        X: [kb64][128m][64k halves], 128B rows, swizzled
//   [131072..196608)   W: 4 quarters x 2 bufs x (32k x 128n), 256B rows, swizzled
//   [196608..198656)   part: float[128][4]
// ============================================================================
#define SM_X    0
#define SM_W    131072
#define SM_PART 196608
#define SMEM_TOTAL 198656
#define NTHREADS 512

__device__ __forceinline__ void fill_w_chunk(const __half* __restrict__ Wh,
                                             uint32_t sb, int q, int qn,
                                             int t, int qt) {
    // t in [0,128): nc = qn*8 + (t>>4), kc = t&15 (32k block), buf = t&1
    int kc = t & 15;
    int nc = qn * 8 + (t >> 4);
    uint32_t base = sb + SM_W + q * 16384 + (t & 1) * 8192;
    const __half* src = Wh + (size_t)(kc * 32) * HID + nc * 128;
#pragma unroll
    for (int i = 0; i < 4; ++i) {
        int idx = i * 128 + qt;                 // 512 chunks of 16B
        int kr = idx >> 4, j = idx & 15;        // kr in [0,32), j in [0,16)
        uint32_t dst = base + kr * 256 + ((j * 16) ^ ((kr & 7) << 4));
        cp_async_16(dst, src + (size_t)kr * HID + j * 8);
    }
}

__global__ void __launch_bounds__(NTHREADS, 1) mhmlp_main(
    const float* __restrict__ b2g, float* __restrict__ out)
{
    extern __shared__ char smem[];
    uint32_t sb = smem_to_u32(smem);
    int tid  = threadIdx.x;
    int lane = tid & 31;
    int wid  = tid >> 5;
    int q    = wid >> 2;        // quarter 0..3  (warps of a quarter span all 4 SMSPs)
    int w4   = wid & 3;         // warp within quarter
    int qm   = q & 1;           // 64-row half
    int qn   = q >> 1;          // 1024-col half
    int wm2  = w4 >> 1;         // 32-row band within 64m
    int wn2  = w4 & 1;          // 64-col half within 128n chunk
    int qt   = tid & 127;       // thread within quarter
    int h  = blockIdx.x >> 4;
    int m0 = (blockIdx.x & 15) * 128;

    const __half* Wh = g_W16 + (size_t)h * DD * HID;

    // ---- X tile fill (all 512 threads): [kb64][m][64k], swizzled 128B rows ----
#pragma unroll
    for (int i = 0; i < 16; ++i) {
        int idx = i * NTHREADS + tid;            // 8192 chunks of 16B
        int m = idx >> 6, j = idx & 63;
        int kb = j >> 3, jj = j & 7;
        uint32_t dst = sb + SM_X + kb * 16384 + m * 128 + ((jj * 16) ^ ((m & 7) << 4));
        cp_async_16(dst, g_X16 + (size_t)(m0 + m) * DD + kb * 64 + jj * 8);
    }
    // ---- each quarter fills its W chunk 0 ----
    fill_w_chunk(Wh, sb, q, qn, 0, qt);
    CP_COMMIT();
    CP_WAIT_ALL();
    __syncthreads();            // X + all W0 chunks visible

    float acc[2][8][4];
#pragma unroll
    for (int mi = 0; mi < 2; ++mi)
#pragma unroll
        for (int ni = 0; ni < 8; ++ni)
#pragma unroll
            for (int r = 0; r < 4; ++r) acc[mi][ni][r] = 0.f;
    float rowacc[4] = {0.f, 0.f, 0.f, 0.f};

    int la = lane & 15;
    int lb = lane >> 4;
    int lmask = (lane & 7) << 4;
    int barid = 1 + q;
    const float4* bw4 = g_BW4 + (size_t)h * (HID / 2);

    uint32_t fa[2][4];
    uint32_t fb[4][4];

    for (int t = 0; t < 128; ++t) {
        if (t > 0) {
            CP_WAIT_ALL();      // W(t) (committed during t-1) is in smem
            asm volatile("bar.sync %0, %1;" :: "r"(barid), "r"(128) : "memory");
        }
        if (t + 1 < 128) fill_w_chunk(Wh, sb, q, qn, t + 1, qt);
        CP_COMMIT();

        int kc = t & 15;
        int nc = qn * 8 + (t >> 4);
        int kb64 = kc >> 1;
        uint32_t abase = sb + SM_X + kb64 * 16384;
        uint32_t bbase = sb + SM_W + q * 16384 + (t & 1) * 8192;

#pragma unroll
        for (int ks = 0; ks < 2; ++ks) {
            int ksg = (kc & 1) * 2 + ks;     // k16 step within the 64k X block
#pragma unroll
            for (int mi = 0; mi < 2; ++mi) {
                int m = qm * 64 + wm2 * 32 + mi * 16 + la;
                uint32_t ad = abase + m * 128 + ((ksg * 32 + lb * 16) ^ lmask);
                LDSM_X4(fa[mi][0], fa[mi][1], fa[mi][2], fa[mi][3], ad);
            }
#pragma unroll
            for (int nb = 0; nb < 4; ++nb) {
                int kr = ks * 16 + la;
                uint32_t bd = bbase + kr * 256 +
                              (((wn2 * 64 + nb * 16 + lb * 8) * 2) ^ lmask);
                LDSM_X4_T(fb[nb][0], fb[nb][1], fb[nb][2], fb[nb][3], bd);
            }
#pragma unroll
            for (int mi = 0; mi < 2; ++mi)
#pragma unroll
                for (int ni = 0; ni < 8; ++ni)
                    mma16816(acc[mi][ni], fa[mi], &fb[ni >> 1][(ni & 1) * 2]);
        }

        if (kc == 15) {
            // fold 128-col n-chunk: bias + leaky + dot(W2)
            int fbase = nc * 64 + wn2 * 32 + (lane & 3);   // float4 index
#pragma unroll
            for (int ni = 0; ni < 8; ++ni) {
                float4 v = bw4[fbase + ni * 4];            // {b1,w2,b1',w2'}
#pragma unroll
                for (int mi = 0; mi < 2; ++mi) {
                    rowacc[mi * 2 + 0] = fmaf(lrelu(acc[mi][ni][0] + v.x), v.y, rowacc[mi * 2 + 0]);
                    rowacc[mi * 2 + 0] = fmaf(lrelu(acc[mi][ni][1] + v.z), v.w, rowacc[mi * 2 + 0]);
                    rowacc[mi * 2 + 1] = fmaf(lrelu(acc[mi][ni][2] + v.x), v.y, rowacc[mi * 2 + 1]);
                    rowacc[mi * 2 + 1] = fmaf(lrelu(acc[mi][ni][3] + v.z), v.w, rowacc[mi * 2 + 1]);
                    acc[mi][ni][0] = 0.f; acc[mi][ni][1] = 0.f;
                    acc[mi][ni][2] = 0.f; acc[mi][ni][3] = 0.f;
                }
            }
        }
    }

    // ---- reduce rowacc across the 4 lanes sharing each row ----
#pragma unroll
    for (int i = 0; i < 4; ++i) {
        rowacc[i] += __shfl_xor_sync(0xffffffffu, rowacc[i], 1);
        rowacc[i] += __shfl_xor_sync(0xffffffffu, rowacc[i], 2);
    }
    float* part = reinterpret_cast<float*>(smem + SM_PART);
    if ((lane & 3) == 0) {
        int rq = lane >> 2;                    // 0..7
        int rbase = qm * 64 + wm2 * 32;
        int col = qn * 2 + wn2;
        part[(rbase +  0 + rq) * 4 + col] = rowacc[0];
        part[(rbase +  8 + rq) * 4 + col] = rowacc[1];
        part[(rbase + 16 + rq) * 4 + col] = rowacc[2];
        part[(rbase + 24 + rq) * 4 + col] = rowacc[3];
    }
    __syncthreads();
    if (tid < 128) {
        float s = part[tid * 4] + part[tid * 4 + 1] + part[tid * 4 + 2] +
                  part[tid * 4 + 3] + b2g[h];
        s = lrelu(s);
        out[(size_t)(m0 + tid) * HH + h] = s;
    }
}

// ============================================================================
// Launch
// ============================================================================
extern "C" void kernel_launch(void* const* d_in, const int* in_sizes, int n_in,
                              void* d_out, int out_size) {
    const float* x  = (const float*)d_in[0];
    const float* W1 = (const float*)d_in[1];
    const float* b1 = (const float*)d_in[2];
    const float* W2 = (const float*)d_in[3];
    const float* b2 = (const float*)d_in[4];
    float* out = (float*)d_out;

    convert_all_kernel<<<33312, 256>>>(x, W1, b1, W2);

    cudaFuncSetAttribute(mhmlp_main, cudaFuncAttributeMaxDynamicSharedMemorySize, SMEM_TOTAL);
    mhmlp_main<<<1024, NTHREADS, SMEM_TOTAL>>>(b2, out);
}

// round 7
// speedup vs baseline: 1.0471x; 1.0471x over previous
#include <cuda_runtime.h>
#include <cuda_fp16.h>
#include <cstdint>

// ============================================================================
// MHMLP: out[b,h] = lrelu( sum_n lrelu( x[b,:]·W1[h,:,n] + b1[h,n] ) * W2[h,n] + b2[h] )
// B=2048, H=64, D=512(K), HID=2048(N). fp32 in/out, fp16 HMMA compute.
// R7 = R5 (two independent halves, 651us, tensor 75.6%) + TRIPLE-buffered W
// per half: prefetch distance 2, wait_group 1 -> consumed chunk committed
// ~4800cyc earlier; top-of-loop wait becomes free, barrier pays only skew.
// ============================================================================
#define BB   2048
#define HH   64
#define DD   512
#define HID  2048

__device__ __half  g_W16[(size_t)HH * DD * HID];    // [h][d][n] fp16
__device__ __half  g_X16[(size_t)BB * DD];          // [b][d]   fp16
__device__ float4  g_BW4[(size_t)HH * HID / 2];     // {b1[n],w2[n],b1[n+1],w2[n+1]}

__device__ __forceinline__ uint32_t smem_to_u32(const void* p) {
    uint32_t a;
    asm("{ .reg .u64 t; cvta.to.shared.u64 t, %1; cvt.u32.u64 %0, t; }" : "=r"(a) : "l"(p));
    return a;
}
__device__ __forceinline__ void cp_async_16(uint32_t dst, const void* src) {
    asm volatile("cp.async.cg.shared.global [%0], [%1], 16;" :: "r"(dst), "l"(src));
}
#define CP_COMMIT()   asm volatile("cp.async.commit_group;" ::: "memory")
#define CP_WAIT(N)    asm volatile("cp.async.wait_group %0;" :: "n"(N) : "memory")

#define LDSM_X4(r0, r1, r2, r3, addr) \
    asm volatile("ldmatrix.sync.aligned.m8n8.x4.shared.b16 {%0,%1,%2,%3}, [%4];" \
        : "=r"(r0), "=r"(r1), "=r"(r2), "=r"(r3) : "r"(addr))
#define LDSM_X4_T(r0, r1, r2, r3, addr) \
    asm volatile("ldmatrix.sync.aligned.m8n8.x4.trans.shared.b16 {%0,%1,%2,%3}, [%4];" \
        : "=r"(r0), "=r"(r1), "=r"(r2), "=r"(r3) : "r"(addr))

__device__ __forceinline__ void mma16816(float* c, const uint32_t* a, const uint32_t* b) {
    asm volatile(
        "mma.sync.aligned.m16n8k16.row.col.f32.f16.f16.f32 "
        "{%0,%1,%2,%3}, {%4,%5,%6,%7}, {%8,%9}, {%0,%1,%2,%3};"
        : "+f"(c[0]), "+f"(c[1]), "+f"(c[2]), "+f"(c[3])
        : "r"(a[0]), "r"(a[1]), "r"(a[2]), "r"(a[3]), "r"(b[0]), "r"(b[1]));
}

__device__ __forceinline__ float lrelu(float v) {
    return fmaxf(v, 0.f) + 0.01f * fminf(v, 0.f);
}

// ============================================================================
// Merged pre-pass:
//   blocks [0,512):       x fp32 -> fp16
//   blocks [512,33280):   W1 fp32 -> fp16
//   blocks [33280,33312): build g_BW4 (b1/W2 interleaved)
// ============================================================================
__global__ void convert_all_kernel(const float* __restrict__ x,
                                   const float* __restrict__ W1,
                                   const float* __restrict__ b1,
                                   const float* __restrict__ w2) {
    if (blockIdx.x >= 33280) {
        int g = (blockIdx.x - 33280) * 256 + threadIdx.x;   // 8192 threads
        float2* bw2 = reinterpret_cast<float2*>(g_BW4);
#pragma unroll
        for (int i = 0; i < 16; ++i) {
            int e = g + i * 8192;                           // HH*HID = 131072
            bw2[e] = make_float2(b1[e], w2[e]);
        }
        return;
    }
    const float* src;
    __half* dst;
    size_t g;
    if (blockIdx.x < 512) {
        g = (size_t)blockIdx.x * 256 + threadIdx.x;
        src = x;  dst = g_X16;
    } else {
        g = (size_t)(blockIdx.x - 512) * 256 + threadIdx.x;
        src = W1; dst = g_W16;
    }
    const float4* p = reinterpret_cast<const float4*>(src) + g * 2;
    float4 a = p[0], b = p[1];
    __half2 h0 = __floats2half2_rn(a.x, a.y), h1 = __floats2half2_rn(a.z, a.w);
    __half2 h2 = __floats2half2_rn(b.x, b.y), h3 = __floats2half2_rn(b.z, b.w);
    uint4 o;
    o.x = *reinterpret_cast<uint32_t*>(&h0);
    o.y = *reinterpret_cast<uint32_t*>(&h1);
    o.z = *reinterpret_cast<uint32_t*>(&h2);
    o.w = *reinterpret_cast<uint32_t*>(&h3);
    *reinterpret_cast<uint4*>(dst + g * 8) = o;
}

// ============================================================================
// Main fused kernel
// Grid: 1024 = 64 heads x 16 m-tiles. 512 threads = 16 warps.
// Warps 0-7 = half 0 (n-chunks 0-7), warps 8-15 = half 1 (n-chunks 8-15).
// Each half: 4m x 2n warps, warp tile 32m x 64n, W TRIPLE buffer (16KB chunks,
// prefetch distance 2), own named barrier, own cp.async groups.
//
// SMEM:
//   [0..131072)        X: [kb][128m][64k halves], 128B rows, swizzled
//   [131072..229376)   W: 2 halves x 3 bufs x (64k x 128n), 256B rows, swizzled
//   [229376..231424)   part: float[128][4]
// ============================================================================
#define SM_X    0
#define SM_W    131072
#define SM_PART 229376
#define SMEM_TOTAL 231424
#define NTHREADS 512

// fill chunk index c (c in [0,64): nc_local=c>>3, kb=c&7) into buffer buf
__device__ __forceinline__ void fill_w_chunk(const __half* __restrict__ Wh,
                                             uint32_t sb, int half, int c,
                                             int buf, int ht) {
    int nc = half * 8 + (c >> 3);
    int kb = c & 7;
    uint32_t base = sb + SM_W + half * 49152 + buf * 16384;
    const __half* src = Wh + (size_t)(kb * 64) * HID + nc * 128;
#pragma unroll
    for (int i = 0; i < 4; ++i) {
        int idx = i * 256 + ht;                 // 1024 chunks of 16B
        int kr = idx >> 4, j = idx & 15;
        uint32_t dst = base + kr * 256 + ((j * 16) ^ ((kr & 7) << 4));
        cp_async_16(dst, src + (size_t)kr * HID + j * 8);
    }
}

__global__ void __launch_bounds__(NTHREADS, 1) mhmlp_main(
    const float* __restrict__ b2g, float* __restrict__ out)
{
    extern __shared__ char smem[];
    uint32_t sb = smem_to_u32(smem);
    int tid  = threadIdx.x;
    int lane = tid & 31;
    int wid  = tid >> 5;
    int half = wid >> 3;        // 0 or 1
    int hw   = wid & 7;         // warp index within half
    int wm   = hw >> 1;         // 0..3 (32-row band)
    int wn   = hw & 1;          // 0..1 (64-col half of the 128n chunk)
    int ht   = tid & 255;       // thread index within half
    int h  = blockIdx.x >> 4;
    int m0 = (blockIdx.x & 15) * 128;

    const __half* Wh = g_W16 + (size_t)h * DD * HID;

    // ---- X tile fill (all 512 threads): [kb][m][64k], swizzled 128B rows ----
#pragma unroll
    for (int i = 0; i < 16; ++i) {
        int idx = i * NTHREADS + tid;            // 8192 chunks of 16B
        int m = idx >> 6, j = idx & 63;
        int kb = j >> 3, jj = j & 7;
        uint32_t dst = sb + SM_X + kb * 16384 + m * 128 + ((jj * 16) ^ ((m & 7) << 4));
        cp_async_16(dst, g_X16 + (size_t)(m0 + m) * DD + kb * 64 + jj * 8);
    }
    // ---- each half fills its W chunks 0 and 1 (bufs 0, 1) ----
    fill_w_chunk(Wh, sb, half, 0, 0, ht);
    CP_COMMIT();                                 // group: X + W0
    fill_w_chunk(Wh, sb, half, 1, 1, ht);
    CP_COMMIT();                                 // group: W1
    CP_WAIT(1);                                  // X + W0 landed
    __syncthreads();

    float acc[2][8][4];
#pragma unroll
    for (int mi = 0; mi < 2; ++mi)
#pragma unroll
        for (int ni = 0; ni < 8; ++ni)
#pragma unroll
            for (int r = 0; r < 4; ++r) acc[mi][ni][r] = 0.f;
    float rowacc[4] = {0.f, 0.f, 0.f, 0.f};

    int la = lane & 15;
    int lb = lane >> 4;
    int lmask = (lane & 7) << 4;
    int barid = 1 + half;
    const float4* bw4 = g_BW4 + (size_t)h * (HID / 2);

    uint32_t fa[2][4];
    uint32_t fb[4][4];

    int bufc = 0;   // buffer holding chunk t (rotates 0,1,2)
    int buff = 2;   // buffer to fill with chunk t+2

    for (int t = 0; t < 64; ++t) {
        if (t > 0) {
            // W(t) was committed at t-2 (or init); newest pending is W(t+1).
            if (t < 63) { CP_WAIT(1); }
            else        { CP_WAIT(0); }
            asm volatile("bar.sync %0, %1;" :: "r"(barid), "r"(256) : "memory");
        }
        if (t + 2 < 64) {
            fill_w_chunk(Wh, sb, half, t + 2, buff, ht);   // buff was read at t-1
            CP_COMMIT();
        }

        int nc = half * 8 + (t >> 3);
        int kb = t & 7;
        uint32_t abase = sb + SM_X + kb * 16384;
        uint32_t bbase = sb + SM_W + half * 49152 + bufc * 16384;

#pragma unroll
        for (int ks = 0; ks < 4; ++ks) {
#pragma unroll
            for (int mi = 0; mi < 2; ++mi) {
                int m = wm * 32 + mi * 16 + la;
                uint32_t ad = abase + m * 128 + ((ks * 32 + lb * 16) ^ lmask);
                LDSM_X4(fa[mi][0], fa[mi][1], fa[mi][2], fa[mi][3], ad);
            }
#pragma unroll
            for (int nb = 0; nb < 4; ++nb) {
                int kr = ks * 16 + la;
                uint32_t bd = bbase + kr * 256 +
                              (((wn * 64 + nb * 16 + lb * 8) * 2) ^ lmask);
                LDSM_X4_T(fb[nb][0], fb[nb][1], fb[nb][2], fb[nb][3], bd);
            }
#pragma unroll
            for (int mi = 0; mi < 2; ++mi)
#pragma unroll
                for (int ni = 0; ni < 8; ++ni)
                    mma16816(acc[mi][ni], fa[mi], &fb[ni >> 1][(ni & 1) * 2]);
        }

        // rotate buffers
        bufc = (bufc == 2) ? 0 : bufc + 1;
        buff = (buff == 2) ? 0 : buff + 1;

        if (kb == 7) {
            // fold 128-col n-chunk: bias + leaky + dot(W2); bw from L2-hot global
            int fbase = nc * 64 + wn * 32 + (lane & 3);   // float4 index
#pragma unroll
            for (int ni = 0; ni < 8; ++ni) {
                float4 v = bw4[fbase + ni * 4];           // {b1,w2,b1',w2'}
#pragma unroll
                for (int mi = 0; mi < 2; ++mi) {
                    rowacc[mi * 2 + 0] = fmaf(lrelu(acc[mi][ni][0] + v.x), v.y, rowacc[mi * 2 + 0]);
                    rowacc[mi * 2 + 0] = fmaf(lrelu(acc[mi][ni][1] + v.z), v.w, rowacc[mi * 2 + 0]);
                    rowacc[mi * 2 + 1] = fmaf(lrelu(acc[mi][ni][2] + v.x), v.y, rowacc[mi * 2 + 1]);
                    rowacc[mi * 2 + 1] = fmaf(lrelu(acc[mi][ni][3] + v.z), v.w, rowacc[mi * 2 + 1]);
                    acc[mi][ni][0] = 0.f; acc[mi][ni][1] = 0.f;
                    acc[mi][ni][2] = 0.f; acc[mi][ni][3] = 0.f;
                }
            }
        }
    }

    // ---- reduce rowacc across the 4 lanes sharing each row ----
#pragma unroll
    for (int i = 0; i < 4; ++i) {
        rowacc[i] += __shfl_xor_sync(0xffffffffu, rowacc[i], 1);
        rowacc[i] += __shfl_xor_sync(0xffffffffu, rowacc[i], 2);
    }
    float* part = reinterpret_cast<float*>(smem + SM_PART);
    if ((lane & 3) == 0) {
        int rq = lane >> 2;                   // 0..7
        int rbase = wm * 32;
        int col = half * 2 + wn;
        part[(rbase +  0 + rq) * 4 + col] = rowacc[0];
        part[(rbase +  8 + rq) * 4 + col] = rowacc[1];
        part[(rbase + 16 + rq) * 4 + col] = rowacc[2];
        part[(rbase + 24 + rq) * 4 + col] = rowacc[3];
    }
    __syncthreads();
    if (tid < 128) {
        float s = part[tid * 4] + part[tid * 4 + 1] + part[tid * 4 + 2] +
                  part[tid * 4 + 3] + b2g[h];
        s = lrelu(s);
        out[(size_t)(m0 + tid) * HH + h] = s;
    }
}

// ============================================================================
// Launch
// ============================================================================
extern "C" void kernel_launch(void* const* d_in, const int* in_sizes, int n_in,
                              void* d_out, int out_size) {
    const float* x  = (const float*)d_in[0];
    const float* W1 = (const float*)d_in[1];
    const float* b1 = (const float*)d_in[2];
    const float* W2 = (const float*)d_in[3];
    const float* b2 = (const float*)d_in[4];
    float* out = (float*)d_out;

    convert_all_kernel<<<33312, 256>>>(x, W1, b1, W2);

    cudaFuncSetAttribute(mhmlp_main, cudaFuncAttributeMaxDynamicSharedMemorySize, SMEM_TOTAL);
    mhmlp_main<<<1024, NTHREADS, SMEM_TOTAL>>>(b2, out);
}

// round 8
// speedup vs baseline: 1.0533x; 1.0060x over previous
#include <cuda_runtime.h>
#include <cuda_fp16.h>
#include <cstdint>

// ============================================================================
// MHMLP: out[b,h] = lrelu( sum_n lrelu( x[b,:]·W1[h,:,n] + b1[h,n] ) * W2[h,n] + b2[h] )
// B=2048, H=64, D=512(K), HID=2048(N). fp32 in/out, fp16 HMMA compute.
// R8 = R5 structure (two independent n-halves, 64 iters of 128n x 64k, W
// double-buffer + named barrier per half) but 8 warps with 64m x 64n warp
// tiles: smem bytes/MMA drop 192 -> 128 (L1 was the hidden co-limiter).
// ============================================================================
#define BB   2048
#define HH   64
#define DD   512
#define HID  2048

__device__ __half  g_W16[(size_t)HH * DD * HID];    // [h][d][n] fp16
__device__ __half  g_X16[(size_t)BB * DD];          // [b][d]   fp16
__device__ float4  g_BW4[(size_t)HH * HID / 2];     // {b1[n],w2[n],b1[n+1],w2[n+1]}

__device__ __forceinline__ uint32_t smem_to_u32(const void* p) {
    uint32_t a;
    asm("{ .reg .u64 t; cvta.to.shared.u64 t, %1; cvt.u32.u64 %0, t; }" : "=r"(a) : "l"(p));
    return a;
}
__device__ __forceinline__ void cp_async_16(uint32_t dst, const void* src) {
    asm volatile("cp.async.cg.shared.global [%0], [%1], 16;" :: "r"(dst), "l"(src));
}
#define CP_COMMIT()   asm volatile("cp.async.commit_group;" ::: "memory")
#define CP_WAIT_ALL() asm volatile("cp.async.wait_group 0;" ::: "memory")

#define LDSM_X4(r0, r1, r2, r3, addr) \
    asm volatile("ldmatrix.sync.aligned.m8n8.x4.shared.b16 {%0,%1,%2,%3}, [%4];" \
        : "=r"(r0), "=r"(r1), "=r"(r2), "=r"(r3) : "r"(addr))
#define LDSM_X4_T(r0, r1, r2, r3, addr) \
    asm volatile("ldmatrix.sync.aligned.m8n8.x4.trans.shared.b16 {%0,%1,%2,%3}, [%4];" \
        : "=r"(r0), "=r"(r1), "=r"(r2), "=r"(r3) : "r"(addr))

__device__ __forceinline__ void mma16816(float* c, const uint32_t* a, const uint32_t* b) {
    asm volatile(
        "mma.sync.aligned.m16n8k16.row.col.f32.f16.f16.f32 "
        "{%0,%1,%2,%3}, {%4,%5,%6,%7}, {%8,%9}, {%0,%1,%2,%3};"
        : "+f"(c[0]), "+f"(c[1]), "+f"(c[2]), "+f"(c[3])
        : "r"(a[0]), "r"(a[1]), "r"(a[2]), "r"(a[3]), "r"(b[0]), "r"(b[1]));
}

__device__ __forceinline__ float lrelu(float v) {
    return fmaxf(v, 0.f) + 0.01f * fminf(v, 0.f);
}

// ============================================================================
// Merged pre-pass:
//   blocks [0,512):       x fp32 -> fp16
//   blocks [512,33280):   W1 fp32 -> fp16
//   blocks [33280,33312): build g_BW4 (b1/W2 interleaved)
// ============================================================================
__global__ void convert_all_kernel(const float* __restrict__ x,
                                   const float* __restrict__ W1,
                                   const float* __restrict__ b1,
                                   const float* __restrict__ w2) {
    if (blockIdx.x >= 33280) {
        int g = (blockIdx.x - 33280) * 256 + threadIdx.x;   // 8192 threads
        float2* bw2 = reinterpret_cast<float2*>(g_BW4);
#pragma unroll
        for (int i = 0; i < 16; ++i) {
            int e = g + i * 8192;                           // HH*HID = 131072
            bw2[e] = make_float2(b1[e], w2[e]);
        }
        return;
    }
    const float* src;
    __half* dst;
    size_t g;
    if (blockIdx.x < 512) {
        g = (size_t)blockIdx.x * 256 + threadIdx.x;
        src = x;  dst = g_X16;
    } else {
        g = (size_t)(blockIdx.x - 512) * 256 + threadIdx.x;
        src = W1; dst = g_W16;
    }
    const float4* p = reinterpret_cast<const float4*>(src) + g * 2;
    float4 a = p[0], b = p[1];
    __half2 h0 = __floats2half2_rn(a.x, a.y), h1 = __floats2half2_rn(a.z, a.w);
    __half2 h2 = __floats2half2_rn(b.x, b.y), h3 = __floats2half2_rn(b.z, b.w);
    uint4 o;
    o.x = *reinterpret_cast<uint32_t*>(&h0);
    o.y = *reinterpret_cast<uint32_t*>(&h1);
    o.z = *reinterpret_cast<uint32_t*>(&h2);
    o.w = *reinterpret_cast<uint32_t*>(&h3);
    *reinterpret_cast<uint4*>(dst + g * 8) = o;
}

// ============================================================================
// Main fused kernel
// Grid: 1024 = 64 heads x 16 m-tiles. 256 threads = 8 warps.
// Warps 0-3 = half 0 (n-chunks 0-7), warps 4-7 = half 1 (n-chunks 8-15).
// Within a half: 2m x 2n warps, warp tile 64m x 64n (128 MMA/warp/iter).
// Each half: own W double buffer (16KB chunks), own named barrier (128 thr),
// own cp.async groups. X tile shared, read-only after init.
//
// SMEM:
//   [0..131072)        X: [kb][128m][64k halves], 128B rows, swizzled
//   [131072..196608)   W: 2 halves x 2 bufs x (64k x 128n), 256B rows, swizzled
//   [196608..198656)   part: float[128][4]
// ============================================================================
#define SM_X    0
#define SM_W    131072
#define SM_PART 196608
#define SMEM_TOTAL 198656
#define NTHREADS 256

// fill chunk c (c in [0,64): nc_local=c>>3, kb=c&7) into buffer (c&1)
__device__ __forceinline__ void fill_w_chunk(const __half* __restrict__ Wh,
                                             uint32_t sb, int half, int c, int ht) {
    int nc = half * 8 + (c >> 3);
    int kb = c & 7;
    uint32_t base = sb + SM_W + half * 32768 + (c & 1) * 16384;
    const __half* src = Wh + (size_t)(kb * 64) * HID + nc * 128;
#pragma unroll
    for (int i = 0; i < 8; ++i) {
        int idx = i * 128 + ht;                 // 1024 chunks of 16B
        int kr = idx >> 4, j = idx & 15;
        uint32_t dst = base + kr * 256 + ((j * 16) ^ ((kr & 7) << 4));
        cp_async_16(dst, src + (size_t)kr * HID + j * 8);
    }
}

__global__ void __launch_bounds__(NTHREADS, 1) mhmlp_main(
    const float* __restrict__ b2g, float* __restrict__ out)
{
    extern __shared__ char smem[];
    uint32_t sb = smem_to_u32(smem);
    int tid  = threadIdx.x;
    int lane = tid & 31;
    int wid  = tid >> 5;
    int half = wid >> 2;        // 0 or 1
    int w4   = wid & 3;         // warp within half
    int wm   = w4 >> 1;         // 0..1 (64-row band)
    int wn   = w4 & 1;          // 0..1 (64-col half of the 128n chunk)
    int ht   = tid & 127;       // thread index within half
    int h  = blockIdx.x >> 4;
    int m0 = (blockIdx.x & 15) * 128;

    const __half* Wh = g_W16 + (size_t)h * DD * HID;

    // ---- X tile fill (all 256 threads): [kb][m][64k], swizzled 128B rows ----
#pragma unroll
    for (int i = 0; i < 32; ++i) {
        int idx = i * NTHREADS + tid;            // 8192 chunks of 16B
        int m = idx >> 6, j = idx & 63;
        int kb = j >> 3, jj = j & 7;
        uint32_t dst = sb + SM_X + kb * 16384 + m * 128 + ((jj * 16) ^ ((m & 7) << 4));
        cp_async_16(dst, g_X16 + (size_t)(m0 + m) * DD + kb * 64 + jj * 8);
    }
    // ---- each half fills its W chunk 0 ----
    fill_w_chunk(Wh, sb, half, 0, ht);
    CP_COMMIT();
    CP_WAIT_ALL();
    __syncthreads();            // X + both W0 chunks visible

    float acc[4][8][4];
#pragma unroll
    for (int mi = 0; mi < 4; ++mi)
#pragma unroll
        for (int ni = 0; ni < 8; ++ni)
#pragma unroll
            for (int r = 0; r < 4; ++r) acc[mi][ni][r] = 0.f;
    float rowacc[8];
#pragma unroll
    for (int i = 0; i < 8; ++i) rowacc[i] = 0.f;

    int la = lane & 15;
    int lb = lane >> 4;
    int lmask = (lane & 7) << 4;
    int barid = 1 + half;
    const float4* bw4 = g_BW4 + (size_t)h * (HID / 2);

    uint32_t fa[4][4];
    uint32_t fb[4][4];

    for (int t = 0; t < 64; ++t) {
        // W(t) ready: committed at top of t-1 (or init for t=0)
        CP_WAIT_ALL();
        asm volatile("bar.sync %0, %1;" :: "r"(barid), "r"(128) : "memory");
        if (t + 1 < 64) fill_w_chunk(Wh, sb, half, t + 1, ht);
        CP_COMMIT();

        int nc = half * 8 + (t >> 3);
        int kb = t & 7;
        uint32_t abase = sb + SM_X + kb * 16384;
        uint32_t bbase = sb + SM_W + half * 32768 + (t & 1) * 16384;

#pragma unroll
        for (int ks = 0; ks < 4; ++ks) {
#pragma unroll
            for (int mi = 0; mi < 4; ++mi) {
                int m = wm * 64 + mi * 16 + la;
                uint32_t ad = abase + m * 128 + ((ks * 32 + lb * 16) ^ lmask);
                LDSM_X4(fa[mi][0], fa[mi][1], fa[mi][2], fa[mi][3], ad);
            }
#pragma unroll
            for (int nb = 0; nb < 4; ++nb) {
                int kr = ks * 16 + la;
                uint32_t bd = bbase + kr * 256 +
                              (((wn * 64 + nb * 16 + lb * 8) * 2) ^ lmask);
                LDSM_X4_T(fb[nb][0], fb[nb][1], fb[nb][2], fb[nb][3], bd);
            }
#pragma unroll
            for (int mi = 0; mi < 4; ++mi)
#pragma unroll
                for (int ni = 0; ni < 8; ++ni)
                    mma16816(acc[mi][ni], fa[mi], &fb[ni >> 1][(ni & 1) * 2]);
        }

        if (kb == 7) {
            // fold 128-col n-chunk: bias + leaky + dot(W2)
            int fbase = nc * 64 + wn * 32 + (lane & 3);   // float4 index
#pragma unroll
            for (int ni = 0; ni < 8; ++ni) {
                float4 v = bw4[fbase + ni * 4];           // {b1,w2,b1',w2'}
#pragma unroll
                for (int mi = 0; mi < 4; ++mi) {
                    rowacc[mi * 2 + 0] = fmaf(lrelu(acc[mi][ni][0] + v.x), v.y, rowacc[mi * 2 + 0]);
                    rowacc[mi * 2 + 0] = fmaf(lrelu(acc[mi][ni][1] + v.z), v.w, rowacc[mi * 2 + 0]);
                    rowacc[mi * 2 + 1] = fmaf(lrelu(acc[mi][ni][2] + v.x), v.y, rowacc[mi * 2 + 1]);
                    rowacc[mi * 2 + 1] = fmaf(lrelu(acc[mi][ni][3] + v.z), v.w, rowacc[mi * 2 + 1]);
                    acc[mi][ni][0] = 0.f; acc[mi][ni][1] = 0.f;
                    acc[mi][ni][2] = 0.f; acc[mi][ni][3] = 0.f;
                }
            }
        }
    }

    // ---- reduce rowacc across the 4 lanes sharing each row ----
#pragma unroll
    for (int i = 0; i < 8; ++i) {
        rowacc[i] += __shfl_xor_sync(0xffffffffu, rowacc[i], 1);
        rowacc[i] += __shfl_xor_sync(0xffffffffu, rowacc[i], 2);
    }
    float* part = reinterpret_cast<float*>(smem + SM_PART);
    if ((lane & 3) == 0) {
        int rq = lane >> 2;                   // 0..7
        int col = half * 2 + wn;
#pragma unroll
        for (int mi = 0; mi < 4; ++mi) {
            int rbase = wm * 64 + mi * 16;
            part[(rbase + 0 + rq) * 4 + col] = rowacc[mi * 2 + 0];
            part[(rbase + 8 + rq) * 4 + col] = rowacc[mi * 2 + 1];
        }
    }
    __syncthreads();
    if (tid < 128) {
        float s = part[tid * 4] + part[tid * 4 + 1] + part[tid * 4 + 2] +
                  part[tid * 4 + 3] + b2g[h];
        s = lrelu(s);
        out[(size_t)(m0 + tid) * HH + h] = s;
    }
}

// ============================================================================
// Launch
// ============================================================================
extern "C" void kernel_launch(void* const* d_in, const int* in_sizes, int n_in,
                              void* d_out, int out_size) {
    const float* x  = (const float*)d_in[0];
    const float* W1 = (const float*)d_in[1];
    const float* b1 = (const float*)d_in[2];
    const float* W2 = (const float*)d_in[3];
    const float* b2 = (const float*)d_in[4];
    float* out = (float*)d_out;

    convert_all_kernel<<<33312, 256>>>(x, W1, b1, W2);

    cudaFuncSetAttribute(mhmlp_main, cudaFuncAttributeMaxDynamicSharedMemorySize, SMEM_TOTAL);
    mhmlp_main<<<1024, NTHREADS, SMEM_TOTAL>>>(b2, out);
}

// round 9
// speedup vs baseline: 1.0886x; 1.0335x over previous
#include <cuda_runtime.h>
#include <cuda_fp16.h>
#include <cstdint>

// ============================================================================
// MHMLP: out[b,h] = lrelu( sum_n lrelu( x[b,:]·W1[h,:,n] + b1[h,n] ) * W2[h,n] + b2[h] )
// B=2048, H=64, D=512(K), HID=2048(N). fp32 in/out, fp16 HMMA compute.
// R9 = R5 (two independent n-halves, 16 warps, 64 iters of 128n x 64k,
// W double-buffer) + producer/consumer SPLIT named barriers:
//   barW[buf]: arrive right after ks loop (reads done), sync before refill
//   barR[buf]: wait_group+arrive at iter end,        sync at next iter top
// Fold moved after the arrives -> its lumpy cost is off the barrier path.
// bw (b1,W2) table in smem (LDS) instead of global (LDG).
// ============================================================================
#define BB   2048
#define HH   64
#define DD   512
#define HID  2048

__device__ __half  g_W16[(size_t)HH * DD * HID];    // [h][d][n] fp16
__device__ __half  g_X16[(size_t)BB * DD];          // [b][d]   fp16

__device__ __forceinline__ uint32_t smem_to_u32(const void* p) {
    uint32_t a;
    asm("{ .reg .u64 t; cvta.to.shared.u64 t, %1; cvt.u32.u64 %0, t; }" : "=r"(a) : "l"(p));
    return a;
}
__device__ __forceinline__ void cp_async_16(uint32_t dst, const void* src) {
    asm volatile("cp.async.cg.shared.global [%0], [%1], 16;" :: "r"(dst), "l"(src));
}
#define CP_COMMIT()   asm volatile("cp.async.commit_group;" ::: "memory")
#define CP_WAIT0()    asm volatile("cp.async.wait_group 0;" ::: "memory")

#define BAR_SYNC(id, cnt) \
    asm volatile("bar.sync %0, %1;" :: "r"(id), "r"(cnt) : "memory")
#define BAR_ARRIVE(id, cnt) \
    asm volatile("bar.arrive %0, %1;" :: "r"(id), "r"(cnt) : "memory")

#define LDSM_X4(r0, r1, r2, r3, addr) \
    asm volatile("ldmatrix.sync.aligned.m8n8.x4.shared.b16 {%0,%1,%2,%3}, [%4];" \
        : "=r"(r0), "=r"(r1), "=r"(r2), "=r"(r3) : "r"(addr))
#define LDSM_X4_T(r0, r1, r2, r3, addr) \
    asm volatile("ldmatrix.sync.aligned.m8n8.x4.trans.shared.b16 {%0,%1,%2,%3}, [%4];" \
        : "=r"(r0), "=r"(r1), "=r"(r2), "=r"(r3) : "r"(addr))

__device__ __forceinline__ void mma16816(float* c, const uint32_t* a, const uint32_t* b) {
    asm volatile(
        "mma.sync.aligned.m16n8k16.row.col.f32.f16.f16.f32 "
        "{%0,%1,%2,%3}, {%4,%5,%6,%7}, {%8,%9}, {%0,%1,%2,%3};"
        : "+f"(c[0]), "+f"(c[1]), "+f"(c[2]), "+f"(c[3])
        : "r"(a[0]), "r"(a[1]), "r"(a[2]), "r"(a[3]), "r"(b[0]), "r"(b[1]));
}

__device__ __forceinline__ float lrelu(float v) {
    return fmaxf(v, 0.f) + 0.01f * fminf(v, 0.f);
}

// ============================================================================
// Merged pre-pass: x fp32->fp16 (blocks [0,512)), W1 fp32->fp16 ([512,33280))
// ============================================================================
__global__ void convert_all_kernel(const float* __restrict__ x,
                                   const float* __restrict__ W1) {
    const float* src;
    __half* dst;
    size_t g;
    if (blockIdx.x < 512) {
        g = (size_t)blockIdx.x * 256 + threadIdx.x;
        src = x;  dst = g_X16;
    } else {
        g = (size_t)(blockIdx.x - 512) * 256 + threadIdx.x;
        src = W1; dst = g_W16;
    }
    const float4* p = reinterpret_cast<const float4*>(src) + g * 2;
    float4 a = p[0], b = p[1];
    __half2 h0 = __floats2half2_rn(a.x, a.y), h1 = __floats2half2_rn(a.z, a.w);
    __half2 h2 = __floats2half2_rn(b.x, b.y), h3 = __floats2half2_rn(b.z, b.w);
    uint4 o;
    o.x = *reinterpret_cast<uint32_t*>(&h0);
    o.y = *reinterpret_cast<uint32_t*>(&h1);
    o.z = *reinterpret_cast<uint32_t*>(&h2);
    o.w = *reinterpret_cast<uint32_t*>(&h3);
    *reinterpret_cast<uint4*>(dst + g * 8) = o;
}

// ============================================================================
// Main fused kernel
// Grid: 1024 = 64 heads x 16 m-tiles. 512 threads = 16 warps.
// Warps 0-7 = half 0 (n-chunks 0-7), warps 8-15 = half 1 (n-chunks 8-15).
// Each half: 4m x 2n warps, warp tile 32m x 64n, W double buffer (16KB chunks),
// split named barriers (arrive/sync, count 512), own cp.async groups.
//
// SMEM:
//   [0..131072)        X: [kb][128m][64k halves], 128B rows, swizzled
//   [131072..196608)   W: 2 halves x 2 bufs x (64k x 128n), 256B rows, swizzled
//   [196608..212992)   bw: float2[2048] = (b1, W2)
//   [212992..215040)   part: float[128][4]
// ============================================================================
#define SM_X    0
#define SM_W    131072
#define SM_BW   196608
#define SM_PART 212992
#define SMEM_TOTAL 215040
#define NTHREADS 512

// fill chunk c (c in [0,64): nc_local=c>>3, kb=c&7) into buffer (c&1)
__device__ __forceinline__ void fill_w_chunk(const __half* __restrict__ Wh,
                                             uint32_t sb, int half, int c, int ht) {
    int nc = half * 8 + (c >> 3);
    int kb = c & 7;
    uint32_t base = sb + SM_W + half * 32768 + (c & 1) * 16384;
    const __half* src = Wh + (size_t)(kb * 64) * HID + nc * 128;
#pragma unroll
    for (int i = 0; i < 4; ++i) {
        int idx = i * 256 + ht;                 // 1024 chunks of 16B
        int kr = idx >> 4, j = idx & 15;
        uint32_t dst = base + kr * 256 + ((j * 16) ^ ((kr & 7) << 4));
        cp_async_16(dst, src + (size_t)kr * HID + j * 8);
    }
}

__global__ void __launch_bounds__(NTHREADS, 1) mhmlp_main(
    const float* __restrict__ b1g, const float* __restrict__ w2g,
    const float* __restrict__ b2g, float* __restrict__ out)
{
    extern __shared__ char smem[];
    uint32_t sb = smem_to_u32(smem);
    int tid  = threadIdx.x;
    int lane = tid & 31;
    int wid  = tid >> 5;
    int half = wid >> 3;        // 0 or 1
    int hw   = wid & 7;         // warp index within half
    int wm   = hw >> 1;         // 0..3 (32-row band)
    int wn   = hw & 1;          // 0..1 (64-col half of the 128n chunk)
    int ht   = tid & 255;       // thread index within half
    int h  = blockIdx.x >> 4;
    int m0 = (blockIdx.x & 15) * 128;

    const __half* Wh = g_W16 + (size_t)h * DD * HID;

    // barrier ids per half: barW[2], barR[2]
    int bW0 = 1 + half * 4, bW1 = 2 + half * 4;
    int bR0 = 3 + half * 4, bR1 = 4 + half * 4;

    // ---- X tile fill (all 512 threads): [kb][m][64k], swizzled 128B rows ----
#pragma unroll
    for (int i = 0; i < 16; ++i) {
        int idx = i * NTHREADS + tid;            // 8192 chunks of 16B
        int m = idx >> 6, j = idx & 63;
        int kb = j >> 3, jj = j & 7;
        uint32_t dst = sb + SM_X + kb * 16384 + m * 128 + ((jj * 16) ^ ((m & 7) << 4));
        cp_async_16(dst, g_X16 + (size_t)(m0 + m) * DD + kb * 64 + jj * 8);
    }
    fill_w_chunk(Wh, sb, half, 0, ht);
    CP_COMMIT();

    // ---- bias/W2 table into smem ----
    float2* bw = reinterpret_cast<float2*>(smem + SM_BW);
#pragma unroll
    for (int i = 0; i < 4; ++i) {
        int n = i * NTHREADS + tid;
        bw[n] = make_float2(b1g[h * HID + n], w2g[h * HID + n]);
    }
    CP_WAIT0();
    __syncthreads();            // X + both W0 chunks + bw visible

    float acc[2][8][4];
#pragma unroll
    for (int mi = 0; mi < 2; ++mi)
#pragma unroll
        for (int ni = 0; ni < 8; ++ni)
#pragma unroll
            for (int r = 0; r < 4; ++r) acc[mi][ni][r] = 0.f;
    float rowacc[4] = {0.f, 0.f, 0.f, 0.f};

    int la = lane & 15;
    int lb = lane >> 4;
    int lmask = (lane & 7) << 4;

    uint32_t fa[2][4];
    uint32_t fb[4][4];

    for (int t = 0; t < 64; ++t) {
        int b  = t & 1;
        int nb = b ^ 1;

        // visibility: everyone's W(t) fills landed (arrived at end of t-1)
        if (t > 0) BAR_SYNC(b ? bR1 : bR0, 512);
        // WAR: readers of buf nb (iter t-1) have finished their LDSMs
        if (t > 0 && t + 1 < 64) BAR_SYNC(nb ? bW1 : bW0, 512);
        // fill W(t+1) into buf nb
        if (t + 1 < 64) {
            fill_w_chunk(Wh, sb, half, t + 1, ht);
            CP_COMMIT();
        }

        int nc = half * 8 + (t >> 3);
        int kb = t & 7;
        uint32_t abase = sb + SM_X + kb * 16384;
        uint32_t bbase = sb + SM_W + half * 32768 + b * 16384;

#pragma unroll
        for (int ks = 0; ks < 4; ++ks) {
#pragma unroll
            for (int mi = 0; mi < 2; ++mi) {
                int m = wm * 32 + mi * 16 + la;
                uint32_t ad = abase + m * 128 + ((ks * 32 + lb * 16) ^ lmask);
                LDSM_X4(fa[mi][0], fa[mi][1], fa[mi][2], fa[mi][3], ad);
            }
#pragma unroll
            for (int nbk = 0; nbk < 4; ++nbk) {
                int kr = ks * 16 + la;
                uint32_t bd = bbase + kr * 256 +
                              (((wn * 64 + nbk * 16 + lb * 8) * 2) ^ lmask);
                LDSM_X4_T(fb[nbk][0], fb[nbk][1], fb[nbk][2], fb[nbk][3], bd);
            }
#pragma unroll
            for (int mi = 0; mi < 2; ++mi)
#pragma unroll
                for (int ni = 0; ni < 8; ++ni)
                    mma16816(acc[mi][ni], fa[mi], &fb[ni >> 1][(ni & 1) * 2]);
        }

        // done reading buf b -> early arrive for the refill at t+1
        BAR_ARRIVE(b ? bW1 : bW0, 512);
        // my W(t+1) fill landed (issued ~1800cyc ago) -> arrive visibility
        if (t + 1 < 64) {
            CP_WAIT0();
            BAR_ARRIVE(nb ? bR1 : bR0, 512);
        }

        // fold AFTER the arrives: its lumpy cost never blocks other warps
        if (kb == 7) {
            int ncb = nc * 128 + wn * 64 + (lane & 3) * 2;
#pragma unroll
            for (int mi = 0; mi < 2; ++mi) {
#pragma unroll
                for (int ni = 0; ni < 8; ++ni) {
                    int n = ncb + ni * 8;
                    float2 p0 = bw[n];
                    float2 p1 = bw[n + 1];
                    rowacc[mi * 2 + 0] = fmaf(lrelu(acc[mi][ni][0] + p0.x), p0.y, rowacc[mi * 2 + 0]);
                    rowacc[mi * 2 + 0] = fmaf(lrelu(acc[mi][ni][1] + p1.x), p1.y, rowacc[mi * 2 + 0]);
                    rowacc[mi * 2 + 1] = fmaf(lrelu(acc[mi][ni][2] + p0.x), p0.y, rowacc[mi * 2 + 1]);
                    rowacc[mi * 2 + 1] = fmaf(lrelu(acc[mi][ni][3] + p1.x), p1.y, rowacc[mi * 2 + 1]);
                    acc[mi][ni][0] = 0.f; acc[mi][ni][1] = 0.f;
                    acc[mi][ni][2] = 0.f; acc[mi][ni][3] = 0.f;
                }
            }
        }
    }

    // ---- reduce rowacc across the 4 lanes sharing each row ----
#pragma unroll
    for (int i = 0; i < 4; ++i) {
        rowacc[i] += __shfl_xor_sync(0xffffffffu, rowacc[i], 1);
        rowacc[i] += __shfl_xor_sync(0xffffffffu, rowacc[i], 2);
    }
    float* part = reinterpret_cast<float*>(smem + SM_PART);
    if ((lane & 3) == 0) {
        int rq = lane >> 2;                   // 0..7
        int rbase = wm * 32;
        int col = half * 2 + wn;
        part[(rbase +  0 + rq) * 4 + col] = rowacc[0];
        part[(rbase +  8 + rq) * 4 + col] = rowacc[1];
        part[(rbase + 16 + rq) * 4 + col] = rowacc[2];
        part[(rbase + 24 + rq) * 4 + col] = rowacc[3];
    }
    __syncthreads();
    if (tid < 128) {
        float s = part[tid * 4] + part[tid * 4 + 1] + part[tid * 4 + 2] +
                  part[tid * 4 + 3] + b2g[h];
        s = lrelu(s);
        out[(size_t)(m0 + tid) * HH + h] = s;
    }
}

// ============================================================================
// Launch
// ============================================================================
extern "C" void kernel_launch(void* const* d_in, const int* in_sizes, int n_in,
                              void* d_out, int out_size) {
    const float* x  = (const float*)d_in[0];
    const float* W1 = (const float*)d_in[1];
    const float* b1 = (const float*)d_in[2];
    const float* W2 = (const float*)d_in[3];
    const float* b2 = (const float*)d_in[4];
    float* out = (float*)d_out;

    convert_all_kernel<<<33280, 256>>>(x, W1);

    cudaFuncSetAttribute(mhmlp_main, cudaFuncAttributeMaxDynamicSharedMemorySize, SMEM_TOTAL);
    mhmlp_main<<<1024, NTHREADS, SMEM_TOTAL>>>(b1, W2, b2, out);
}